// round 1
// baseline (speedup 1.0000x reference)
#include <cuda_runtime.h>

// Problem constants
#define B_   2
#define S_   2048
#define D_   1024
#define H_   16
#define HD_  64
#define MTOK (B_ * S_)      // 4096 tokens
#define SCALE_ 0.125f       // 64^-0.5

// Intermediate buffers (no cudaMalloc allowed -> device globals)
__device__ float g_qh[(size_t)B_ * H_ * S_ * HD_];   // [B,H,S,HD]
__device__ float g_kh[(size_t)B_ * H_ * S_ * HD_];
__device__ float g_vh[(size_t)B_ * H_ * S_ * HD_];
__device__ float g_att[(size_t)MTOK * D_];           // [B,S,D] merged heads

// ---------------------------------------------------------------------------
// SGEMM: C = A[M,K] @ W[N,K]^T + bias, M=4096, N=K=1024.
// 128x128 tile, BK=16, 256 threads, 8x8 per thread.
// out_mode: 0->g_qh, 1->g_kh, 2->g_vh (head layout [B,H,S,HD]); 3->C_ext [M,N]
// A_ext == nullptr -> read from g_att.
// ---------------------------------------------------------------------------
__global__ __launch_bounds__(256) void sgemm_kernel(
    const float* __restrict__ A_ext,
    const float* __restrict__ W,
    const float* __restrict__ bias,
    float* __restrict__ C_ext,
    int out_mode)
{
    const int K = 1024;
    const float* __restrict__ A = A_ext ? A_ext : g_att;

    __shared__ float As[16][132];
    __shared__ float Bs[16][132];

    const int tid = threadIdx.x;
    const int tx = tid & 15;        // n sub-tile
    const int ty = tid >> 4;        // m sub-tile
    const int bm = blockIdx.x * 128;
    const int bn = blockIdx.y * 128;

    const int lrow = tid >> 2;            // 0..63
    const int lk   = (tid & 3) * 4;       // 0,4,8,12

    float acc[8][8];
#pragma unroll
    for (int i = 0; i < 8; i++)
#pragma unroll
        for (int j = 0; j < 8; j++) acc[i][j] = 0.f;

    for (int k0 = 0; k0 < K; k0 += 16) {
#pragma unroll
        for (int r = 0; r < 2; r++) {
            int row = lrow + r * 64;
            float4 a = *(const float4*)&A[(size_t)(bm + row) * K + k0 + lk];
            As[lk + 0][row] = a.x; As[lk + 1][row] = a.y;
            As[lk + 2][row] = a.z; As[lk + 3][row] = a.w;
            float4 b = *(const float4*)&W[(size_t)(bn + row) * K + k0 + lk];
            Bs[lk + 0][row] = b.x; Bs[lk + 1][row] = b.y;
            Bs[lk + 2][row] = b.z; Bs[lk + 3][row] = b.w;
        }
        __syncthreads();

#pragma unroll
        for (int k = 0; k < 16; k++) {
            float a[8], b[8];
            *(float4*)&a[0] = *(float4*)&As[k][ty * 8];
            *(float4*)&a[4] = *(float4*)&As[k][ty * 8 + 4];
            *(float4*)&b[0] = *(float4*)&Bs[k][tx * 8];
            *(float4*)&b[4] = *(float4*)&Bs[k][tx * 8 + 4];
#pragma unroll
            for (int i = 0; i < 8; i++)
#pragma unroll
                for (int j = 0; j < 8; j++)
                    acc[i][j] += a[i] * b[j];
        }
        __syncthreads();
    }

    // epilogue
#pragma unroll
    for (int i = 0; i < 8; i++) {
        const int m = bm + ty * 8 + i;
        const int b = m >> 11;          // m / S_
        const int s = m & (S_ - 1);
#pragma unroll
        for (int j = 0; j < 8; j++) {
            const int n = bn + tx * 8 + j;
            float v = acc[i][j] + bias[n];
            if (out_mode < 3) {
                const int h  = n >> 6;
                const int hd = n & 63;
                float* dst = (out_mode == 0) ? g_qh : (out_mode == 1) ? g_kh : g_vh;
                dst[((size_t)(b * H_ + h) * S_ + s) * HD_ + hd] = v;
            } else {
                C_ext[(size_t)m * D_ + n] = v;
            }
        }
    }
}

// ---------------------------------------------------------------------------
// Flash attention, causal, fp32. One block = 64 queries of one (b,h).
// 256 threads: tx = tid&15 (4 key/d cols each), ty = tid>>4 (4 q rows each).
// Smem strides of 68 floats (bank-conflict-free for the access patterns used).
// ---------------------------------------------------------------------------
#define FSTR 68
__global__ __launch_bounds__(256) void flash_kernel()
{
    extern __shared__ float sm[];
    float (*Qs)[FSTR] = (float(*)[FSTR])(sm);
    float (*Ks)[FSTR] = (float(*)[FSTR])(sm + 64 * FSTR);      // Ks[d][key]
    float (*Vs)[FSTR] = (float(*)[FSTR])(sm + 2 * 64 * FSTR);  // Vs[key][d]
    float (*Ps)[FSTR] = (float(*)[FSTR])(sm + 3 * 64 * FSTR);  // Ps[q][key]

    const int qt = blockIdx.x;     // 0..31
    const int h  = blockIdx.y;
    const int b  = blockIdx.z;
    const int tid = threadIdx.x;
    const int tx = tid & 15;
    const int ty = tid >> 4;

    const size_t head_off = (size_t)(b * H_ + h) * S_ * HD_;
    const float* __restrict__ Qb = g_qh + head_off;
    const float* __restrict__ Kb = g_kh + head_off;
    const float* __restrict__ Vb = g_vh + head_off;

    const int q0 = qt * 64;

    // load Q tile [64 x 64]
    {
        const int row = tid >> 2;
        const int c   = (tid & 3) * 16;
        const float* src = Qb + (size_t)(q0 + row) * HD_ + c;
#pragma unroll
        for (int u = 0; u < 4; u++)
            *(float4*)&Qs[row][c + 4 * u] = *(const float4*)(src + 4 * u);
    }

    float m_i[4], l_i[4], o[4][4];
#pragma unroll
    for (int i = 0; i < 4; i++) {
        m_i[i] = -1e30f; l_i[i] = 0.f;
#pragma unroll
        for (int j = 0; j < 4; j++) o[i][j] = 0.f;
    }

    for (int jt = 0; jt <= qt; jt++) {
        const int k0 = jt * 64;
        __syncthreads();   // prior-iter reads done (also fences Q writes, iter 0)

        // load K (transposed: Ks[d][key]) and V (natural: Vs[key][d])
        {
            const int row = tid >> 2;
            const int c   = (tid & 3) * 16;
            const float* ksrc = Kb + (size_t)(k0 + row) * HD_ + c;
            const float* vsrc = Vb + (size_t)(k0 + row) * HD_ + c;
#pragma unroll
            for (int u = 0; u < 4; u++) {
                float4 kv = *(const float4*)(ksrc + 4 * u);
                Ks[c + 4 * u + 0][row] = kv.x;
                Ks[c + 4 * u + 1][row] = kv.y;
                Ks[c + 4 * u + 2][row] = kv.z;
                Ks[c + 4 * u + 3][row] = kv.w;
                *(float4*)&Vs[row][c + 4 * u] = *(const float4*)(vsrc + 4 * u);
            }
        }
        __syncthreads();

        // scores: acc[i][j] = sum_d Q[q_i][d] * K[k_j][d]
        float acc[4][4];
#pragma unroll
        for (int i = 0; i < 4; i++)
#pragma unroll
            for (int j = 0; j < 4; j++) acc[i][j] = 0.f;

#pragma unroll 16
        for (int d = 0; d < 64; d++) {
            float4 kv4 = *(float4*)&Ks[d][tx * 4];
            float kk[4] = {kv4.x, kv4.y, kv4.z, kv4.w};
            float qv[4];
#pragma unroll
            for (int i = 0; i < 4; i++) qv[i] = Qs[ty * 4 + i][d];
#pragma unroll
            for (int i = 0; i < 4; i++)
#pragma unroll
                for (int j = 0; j < 4; j++)
                    acc[i][j] += qv[i] * kk[j];
        }

        // mask + scale + online softmax + write P
        const bool diag = (jt == qt);
#pragma unroll
        for (int i = 0; i < 4; i++) {
            const int qrow = q0 + ty * 4 + i;
            float mx = -1e30f;
#pragma unroll
            for (int j = 0; j < 4; j++) {
                float s = acc[i][j] * SCALE_;
                if (diag && (k0 + tx * 4 + j) > qrow) s = -1e30f;
                acc[i][j] = s;
                mx = fmaxf(mx, s);
            }
#pragma unroll
            for (int off = 8; off > 0; off >>= 1)
                mx = fmaxf(mx, __shfl_xor_sync(0xffffffffu, mx, off));
            const float m_new = fmaxf(m_i[i], mx);
            const float f = __expf(m_i[i] - m_new);
            m_i[i] = m_new;
            l_i[i] *= f;
            float rs = 0.f;
#pragma unroll
            for (int j = 0; j < 4; j++) {
                float p = __expf(acc[i][j] - m_new);
                acc[i][j] = p;
                rs += p;
            }
#pragma unroll
            for (int off = 8; off > 0; off >>= 1)
                rs += __shfl_xor_sync(0xffffffffu, rs, off);
            l_i[i] += rs;
#pragma unroll
            for (int j = 0; j < 4; j++) o[i][j] *= f;
            *(float4*)&Ps[ty * 4 + i][tx * 4] =
                make_float4(acc[i][0], acc[i][1], acc[i][2], acc[i][3]);
        }
        __syncthreads();

        // O += P @ V  (o[i][j]: rows q, cols d = tx*4+j)
#pragma unroll 4
        for (int kk = 0; kk < 64; kk += 4) {
            float p4[4][4];
#pragma unroll
            for (int i = 0; i < 4; i++)
                *(float4*)p4[i] = *(float4*)&Ps[ty * 4 + i][kk];
#pragma unroll
            for (int u = 0; u < 4; u++) {
                float4 vv = *(float4*)&Vs[kk + u][tx * 4];
                float vp[4] = {vv.x, vv.y, vv.z, vv.w};
#pragma unroll
                for (int i = 0; i < 4; i++)
#pragma unroll
                    for (int j = 0; j < 4; j++)
                        o[i][j] += p4[i][u] * vp[j];
            }
        }
    }

    // normalize + write merged-head output [B,S,D]
#pragma unroll
    for (int i = 0; i < 4; i++) {
        const float inv = 1.f / l_i[i];
        const int s = q0 + ty * 4 + i;
        float4 res = make_float4(o[i][0] * inv, o[i][1] * inv,
                                 o[i][2] * inv, o[i][3] * inv);
        *(float4*)&g_att[((size_t)b * S_ + s) * D_ + h * HD_ + tx * 4] = res;
    }
}

// ---------------------------------------------------------------------------
// Launch
// Inputs: 0:q 1:k 2:v 3:attn_mask(ignored; causal known) 4:Wq 5:bq 6:Wk 7:bk
//         8:Wv 9:bv 10:Wo 11:bo
// ---------------------------------------------------------------------------
extern "C" void kernel_launch(void* const* d_in, const int* in_sizes, int n_in,
                              void* d_out, int out_size)
{
    const float* q  = (const float*)d_in[0];
    const float* k  = (const float*)d_in[1];
    const float* v  = (const float*)d_in[2];
    const float* Wq = (const float*)d_in[4];
    const float* bq = (const float*)d_in[5];
    const float* Wk = (const float*)d_in[6];
    const float* bk = (const float*)d_in[7];
    const float* Wv = (const float*)d_in[8];
    const float* bv = (const float*)d_in[9];
    const float* Wo = (const float*)d_in[10];
    const float* bo = (const float*)d_in[11];
    float* out = (float*)d_out;

    dim3 gg(MTOK / 128, D_ / 128);   // 32 x 8
    sgemm_kernel<<<gg, 256>>>(q, Wq, bq, nullptr, 0);
    sgemm_kernel<<<gg, 256>>>(k, Wk, bk, nullptr, 1);
    sgemm_kernel<<<gg, 256>>>(v, Wv, bv, nullptr, 2);

    static bool attr_done = false;
    const int fl_smem = 4 * 64 * FSTR * (int)sizeof(float);  // 69632 B
    if (!attr_done) {
        cudaFuncSetAttribute(flash_kernel,
                             cudaFuncAttributeMaxDynamicSharedMemorySize, fl_smem);
        attr_done = true;
    }
    dim3 gf(S_ / 64, H_, B_);        // 32 x 16 x 2
    flash_kernel<<<gf, 256, fl_smem>>>();

    sgemm_kernel<<<gg, 256>>>(nullptr, Wo, bo, out, 3);
}

// round 4
// speedup vs baseline: 1.4548x; 1.4548x over previous
#include <cuda_runtime.h>
#include <cuda_bf16.h>
#include <cstdint>

// Problem constants
#define B_   2
#define S_   2048
#define D_   1024
#define H_   16
#define HD_  64
#define MTOK (B_ * S_)      // 4096 tokens
#define SCALE_ 0.125f       // 64^-0.5

// ---------------------------------------------------------------------------
// Device-global scratch (no cudaMalloc allowed)
// ---------------------------------------------------------------------------
__device__ float g_qh[(size_t)B_ * H_ * S_ * HD_];   // [B,H,S,HD]
__device__ float g_kh[(size_t)B_ * H_ * S_ * HD_];
__device__ float g_vh[(size_t)B_ * H_ * S_ * HD_];
__device__ float g_att[(size_t)MTOK * D_];           // [B,S,D] merged heads

// bf16 split buffers
__device__ __nv_bfloat16 g_q_hi[(size_t)MTOK * D_],  g_q_lo[(size_t)MTOK * D_];
__device__ __nv_bfloat16 g_k_hi[(size_t)MTOK * D_],  g_k_lo[(size_t)MTOK * D_];
__device__ __nv_bfloat16 g_v_hi[(size_t)MTOK * D_],  g_v_lo[(size_t)MTOK * D_];
__device__ __nv_bfloat16 g_a_hi[(size_t)MTOK * D_],  g_a_lo[(size_t)MTOK * D_];
__device__ __nv_bfloat16 g_wq_hi[(size_t)D_ * D_],   g_wq_lo[(size_t)D_ * D_];
__device__ __nv_bfloat16 g_wk_hi[(size_t)D_ * D_],   g_wk_lo[(size_t)D_ * D_];
__device__ __nv_bfloat16 g_wv_hi[(size_t)D_ * D_],   g_wv_lo[(size_t)D_ * D_];
__device__ __nv_bfloat16 g_wo_hi[(size_t)D_ * D_],   g_wo_lo[(size_t)D_ * D_];

// ---------------------------------------------------------------------------
// Helpers
// ---------------------------------------------------------------------------
__device__ __forceinline__ uint32_t smem_u32(const void* p) {
    uint32_t a;
    asm("{ .reg .u64 t; cvta.to.shared.u64 t, %1; cvt.u32.u64 %0, t; }"
        : "=r"(a) : "l"(p));
    return a;
}

#define SWZ128(off) ((uint32_t)(off) ^ ((((uint32_t)(off)) >> 3) & 0x70u))

__device__ __forceinline__ void ldm_x4(uint32_t r[4], uint32_t addr) {
    asm volatile("ldmatrix.sync.aligned.m8n8.x4.shared.b16 {%0,%1,%2,%3}, [%4];"
        : "=r"(r[0]), "=r"(r[1]), "=r"(r[2]), "=r"(r[3]) : "r"(addr));
}

__device__ __forceinline__ void mma_bf16(float c[4], const uint32_t a[4],
                                         uint32_t b0, uint32_t b1) {
    asm volatile(
        "mma.sync.aligned.m16n8k16.row.col.f32.bf16.bf16.f32 "
        "{%0,%1,%2,%3}, {%4,%5,%6,%7}, {%8,%9}, {%0,%1,%2,%3};"
        : "+f"(c[0]), "+f"(c[1]), "+f"(c[2]), "+f"(c[3])
        : "r"(a[0]), "r"(a[1]), "r"(a[2]), "r"(a[3]), "r"(b0), "r"(b1));
}

// ---------------------------------------------------------------------------
// fp32 -> (hi, lo) bf16 split, vectorized x4
// ---------------------------------------------------------------------------
__global__ __launch_bounds__(256) void split_bf16_kernel(
    const float* __restrict__ x,
    __nv_bfloat16* __restrict__ hi, __nv_bfloat16* __restrict__ lo, int n4)
{
    int i = blockIdx.x * blockDim.x + threadIdx.x;
    if (i >= n4) return;
    float4 v = ((const float4*)x)[i];
    float f[4] = {v.x, v.y, v.z, v.w};
    unsigned short hu[4], lu[4];
#pragma unroll
    for (int c = 0; c < 4; c++) {
        __nv_bfloat16 h = __float2bfloat16(f[c]);
        __nv_bfloat16 l = __float2bfloat16(f[c] - __bfloat162float(h));
        hu[c] = __bfloat16_as_ushort(h);
        lu[c] = __bfloat16_as_ushort(l);
    }
    ((ushort4*)hi)[i] = make_ushort4(hu[0], hu[1], hu[2], hu[3]);
    ((ushort4*)lo)[i] = make_ushort4(lu[0], lu[1], lu[2], lu[3]);
}

// ---------------------------------------------------------------------------
// HMMA bf16-split GEMM: C[M,N] = A[M,K] @ W[N,K]^T + bias
// M=4096, N=K=1024.  CTA tile 128x128, K-chunk 64, 8 warps (2x4),
// warp tile 64x32 via mma.m16n8k16, 3-term bf16 split, fp32 accum.
// out_mode: 0/1/2 -> g_qh/g_kh/g_vh in [B,H,S,HD] layout; 3 -> Cext [M,N].
// ---------------------------------------------------------------------------
#define GTM 128
#define GTN 128
#define GKC 64
#define GK  1024
#define GEMM_SMEM 66560   // 1KB bias/pad + 4 x 16KB tiles

__global__ __launch_bounds__(256) void gemm_hmma_kernel(
    const __nv_bfloat16* __restrict__ Ah, const __nv_bfloat16* __restrict__ Al,
    const __nv_bfloat16* __restrict__ Wh, const __nv_bfloat16* __restrict__ Wl,
    const float* __restrict__ bias, float* __restrict__ Cext, int out_mode)
{
    extern __shared__ char smem[];
    const uint32_t sb = smem_u32(smem);
    float* sbias = (float*)smem;

    const int tid  = threadIdx.x;
    const int lane = tid & 31;
    const int wid  = tid >> 5;
    const int warp_m = wid >> 2;      // 0..1
    const int warp_n = wid & 3;       // 0..3
    const int bm = blockIdx.x * GTM;
    const int bn = blockIdx.y * GTN;

    const uint32_t SA_HI = 1024;      // 128 rows * 128B = 16 KB each
    const uint32_t SA_LO = 17408;
    const uint32_t SW_HI = 33792;
    const uint32_t SW_LO = 50176;

    if (tid < GTN) sbias[tid] = bias[bn + tid];

    float acc[4][4][4];
#pragma unroll
    for (int a = 0; a < 4; a++)
#pragma unroll
        for (int b = 0; b < 4; b++)
#pragma unroll
            for (int c = 0; c < 4; c++) acc[a][b][c] = 0.f;

    for (int kc = 0; kc < GK / GKC; kc++) {
        const int k0 = kc * GKC;
        // cooperative tile loads: 4 tiles x 1024 16B-vectors
#pragma unroll
        for (int v = tid; v < 1024; v += 256) {
            const int row = v >> 3, seg = v & 7;
            const uint32_t so = SWZ128(row * 128 + seg * 16);
            const size_t ga = (size_t)(bm + row) * GK + k0 + seg * 8;
            const size_t gw = (size_t)(bn + row) * GK + k0 + seg * 8;
            *(uint4*)(smem + SA_HI + so) = *(const uint4*)(Ah + ga);
            *(uint4*)(smem + SA_LO + so) = *(const uint4*)(Al + ga);
            *(uint4*)(smem + SW_HI + so) = *(const uint4*)(Wh + gw);
            *(uint4*)(smem + SW_LO + so) = *(const uint4*)(Wl + gw);
        }
        __syncthreads();

#pragma unroll
        for (int s = 0; s < 4; s++) {     // 4 x k16 within the 64-chunk
            uint32_t ah[4][4], alr[4][4], bh[2][4], bl[2][4];
            const int arow = lane & 15;
            const int aseg = s * 2 + (lane >> 4);
#pragma unroll
            for (int t = 0; t < 4; t++) {
                const uint32_t off =
                    SWZ128((warp_m * 64 + t * 16 + arow) * 128 + aseg * 16);
                ldm_x4(ah[t],  sb + SA_HI + off);
                ldm_x4(alr[t], sb + SA_LO + off);
            }
            const int brow = (lane & 7) + ((lane & 16) >> 1);
            const int bseg = s * 2 + ((lane >> 3) & 1);
#pragma unroll
            for (int p = 0; p < 2; p++) {
                const uint32_t off =
                    SWZ128((warp_n * 32 + p * 16 + brow) * 128 + bseg * 16);
                ldm_x4(bh[p], sb + SW_HI + off);
                ldm_x4(bl[p], sb + SW_LO + off);
            }
#pragma unroll
            for (int mt = 0; mt < 4; mt++)
#pragma unroll
                for (int nt = 0; nt < 4; nt++) {
                    const int p = nt >> 1, q = (nt & 1) * 2;
                    mma_bf16(acc[mt][nt], ah[mt],  bh[p][q], bh[p][q + 1]);
                    mma_bf16(acc[mt][nt], ah[mt],  bl[p][q], bl[p][q + 1]);
                    mma_bf16(acc[mt][nt], alr[mt], bh[p][q], bh[p][q + 1]);
                }
        }
        __syncthreads();
    }

    // epilogue: c0,c1 -> (row g, cols 2tg..+1); c2,c3 -> (row g+8)
    const int group = lane >> 2, tg = lane & 3;
#pragma unroll
    for (int mt = 0; mt < 4; mt++) {
#pragma unroll
        for (int nt = 0; nt < 4; nt++) {
            const int m0 = bm + warp_m * 64 + mt * 16 + group;
            const int n0 = bn + warp_n * 32 + nt * 8 + tg * 2;
            const float bv0 = sbias[n0 - bn];
            const float bv1 = sbias[n0 - bn + 1];
            const float* cv = acc[mt][nt];
            if (out_mode < 3) {
                const int h = n0 >> 6, hd = n0 & 63;
                float* base = (out_mode == 0) ? g_qh : (out_mode == 1) ? g_kh : g_vh;
#pragma unroll
                for (int r = 0; r < 2; r++) {
                    const int m = m0 + r * 8;
                    const int b = m >> 11, sq = m & (S_ - 1);
                    float2 w = make_float2(cv[r * 2 + 0] + bv0, cv[r * 2 + 1] + bv1);
                    *(float2*)(base + ((size_t)(b * H_ + h) * S_ + sq) * HD_ + hd) = w;
                }
            } else {
#pragma unroll
                for (int r = 0; r < 2; r++) {
                    const int m = m0 + r * 8;
                    float2 w = make_float2(cv[r * 2 + 0] + bv0, cv[r * 2 + 1] + bv1);
                    *(float2*)(Cext + (size_t)m * D_ + n0) = w;
                }
            }
        }
    }
}

// ---------------------------------------------------------------------------
// Flash attention, causal, fp32 (unchanged — verified, 699us).
// ---------------------------------------------------------------------------
#define FSTR 68
__global__ __launch_bounds__(256) void flash_kernel()
{
    extern __shared__ float sm[];
    float (*Qs)[FSTR] = (float(*)[FSTR])(sm);
    float (*Ks)[FSTR] = (float(*)[FSTR])(sm + 64 * FSTR);      // Ks[d][key]
    float (*Vs)[FSTR] = (float(*)[FSTR])(sm + 2 * 64 * FSTR);  // Vs[key][d]
    float (*Ps)[FSTR] = (float(*)[FSTR])(sm + 3 * 64 * FSTR);  // Ps[q][key]

    const int qt = blockIdx.x;
    const int h  = blockIdx.y;
    const int b  = blockIdx.z;
    const int tid = threadIdx.x;
    const int tx = tid & 15;
    const int ty = tid >> 4;

    const size_t head_off = (size_t)(b * H_ + h) * S_ * HD_;
    const float* __restrict__ Qb = g_qh + head_off;
    const float* __restrict__ Kb = g_kh + head_off;
    const float* __restrict__ Vb = g_vh + head_off;

    const int q0 = qt * 64;

    {
        const int row = tid >> 2;
        const int c   = (tid & 3) * 16;
        const float* src = Qb + (size_t)(q0 + row) * HD_ + c;
#pragma unroll
        for (int u = 0; u < 4; u++)
            *(float4*)&Qs[row][c + 4 * u] = *(const float4*)(src + 4 * u);
    }

    float m_i[4], l_i[4], o[4][4];
#pragma unroll
    for (int i = 0; i < 4; i++) {
        m_i[i] = -1e30f; l_i[i] = 0.f;
#pragma unroll
        for (int j = 0; j < 4; j++) o[i][j] = 0.f;
    }

    for (int jt = 0; jt <= qt; jt++) {
        const int k0 = jt * 64;
        __syncthreads();

        {
            const int row = tid >> 2;
            const int c   = (tid & 3) * 16;
            const float* ksrc = Kb + (size_t)(k0 + row) * HD_ + c;
            const float* vsrc = Vb + (size_t)(k0 + row) * HD_ + c;
#pragma unroll
            for (int u = 0; u < 4; u++) {
                float4 kv = *(const float4*)(ksrc + 4 * u);
                Ks[c + 4 * u + 0][row] = kv.x;
                Ks[c + 4 * u + 1][row] = kv.y;
                Ks[c + 4 * u + 2][row] = kv.z;
                Ks[c + 4 * u + 3][row] = kv.w;
                *(float4*)&Vs[row][c + 4 * u] = *(const float4*)(vsrc + 4 * u);
            }
        }
        __syncthreads();

        float acc[4][4];
#pragma unroll
        for (int i = 0; i < 4; i++)
#pragma unroll
            for (int j = 0; j < 4; j++) acc[i][j] = 0.f;

#pragma unroll 16
        for (int d = 0; d < 64; d++) {
            float4 kv4 = *(float4*)&Ks[d][tx * 4];
            float kk[4] = {kv4.x, kv4.y, kv4.z, kv4.w};
            float qv[4];
#pragma unroll
            for (int i = 0; i < 4; i++) qv[i] = Qs[ty * 4 + i][d];
#pragma unroll
            for (int i = 0; i < 4; i++)
#pragma unroll
                for (int j = 0; j < 4; j++)
                    acc[i][j] += qv[i] * kk[j];
        }

        const bool diag = (jt == qt);
#pragma unroll
        for (int i = 0; i < 4; i++) {
            const int qrow = q0 + ty * 4 + i;
            float mx = -1e30f;
#pragma unroll
            for (int j = 0; j < 4; j++) {
                float s = acc[i][j] * SCALE_;
                if (diag && (k0 + tx * 4 + j) > qrow) s = -1e30f;
                acc[i][j] = s;
                mx = fmaxf(mx, s);
            }
#pragma unroll
            for (int off = 8; off > 0; off >>= 1)
                mx = fmaxf(mx, __shfl_xor_sync(0xffffffffu, mx, off));
            const float m_new = fmaxf(m_i[i], mx);
            const float f = __expf(m_i[i] - m_new);
            m_i[i] = m_new;
            l_i[i] *= f;
            float rs = 0.f;
#pragma unroll
            for (int j = 0; j < 4; j++) {
                float p = __expf(acc[i][j] - m_new);
                acc[i][j] = p;
                rs += p;
            }
#pragma unroll
            for (int off = 8; off > 0; off >>= 1)
                rs += __shfl_xor_sync(0xffffffffu, rs, off);
            l_i[i] += rs;
#pragma unroll
            for (int j = 0; j < 4; j++) o[i][j] *= f;
            *(float4*)&Ps[ty * 4 + i][tx * 4] =
                make_float4(acc[i][0], acc[i][1], acc[i][2], acc[i][3]);
        }
        __syncthreads();

#pragma unroll 4
        for (int kk = 0; kk < 64; kk += 4) {
            float p4[4][4];
#pragma unroll
            for (int i = 0; i < 4; i++)
                *(float4*)p4[i] = *(float4*)&Ps[ty * 4 + i][kk];
#pragma unroll
            for (int u = 0; u < 4; u++) {
                float4 vv = *(float4*)&Vs[kk + u][tx * 4];
                float vp[4] = {vv.x, vv.y, vv.z, vv.w};
#pragma unroll
                for (int i = 0; i < 4; i++)
#pragma unroll
                    for (int j = 0; j < 4; j++)
                        o[i][j] += p4[i][u] * vp[j];
            }
        }
    }

#pragma unroll
    for (int i = 0; i < 4; i++) {
        const float inv = 1.f / l_i[i];
        const int s = q0 + ty * 4 + i;
        float4 res = make_float4(o[i][0] * inv, o[i][1] * inv,
                                 o[i][2] * inv, o[i][3] * inv);
        *(float4*)&g_att[((size_t)b * S_ + s) * D_ + h * HD_ + tx * 4] = res;
    }
}

// ---------------------------------------------------------------------------
// Launch.  Inputs: 0:q 1:k 2:v 3:attn_mask 4:Wq 5:bq 6:Wk 7:bk 8:Wv 9:bv 10:Wo 11:bo
// ---------------------------------------------------------------------------
extern "C" void kernel_launch(void* const* d_in, const int* in_sizes, int n_in,
                              void* d_out, int out_size)
{
    const float* q  = (const float*)d_in[0];
    const float* k  = (const float*)d_in[1];
    const float* v  = (const float*)d_in[2];
    const float* Wq = (const float*)d_in[4];
    const float* bq = (const float*)d_in[5];
    const float* Wk = (const float*)d_in[6];
    const float* bk = (const float*)d_in[7];
    const float* Wv = (const float*)d_in[8];
    const float* bv = (const float*)d_in[9];
    const float* Wo = (const float*)d_in[10];
    const float* bo = (const float*)d_in[11];
    float* out = (float*)d_out;

    static bool attr_done = false;
    const int fl_smem = 4 * 64 * FSTR * (int)sizeof(float);  // 69632 B
    if (!attr_done) {
        cudaFuncSetAttribute(flash_kernel,
                             cudaFuncAttributeMaxDynamicSharedMemorySize, fl_smem);
        cudaFuncSetAttribute(gemm_hmma_kernel,
                             cudaFuncAttributeMaxDynamicSharedMemorySize, GEMM_SMEM);
        attr_done = true;
    }

    // resolve device-global bf16 buffer addresses (host-side)
    __nv_bfloat16 *qh, *ql, *kh, *kl, *vh, *vl, *ah, *al;
    __nv_bfloat16 *wqh, *wql, *wkh, *wkl, *wvh, *wvl, *woh, *wol;
    float* gatt;
    cudaGetSymbolAddress((void**)&qh, g_q_hi);  cudaGetSymbolAddress((void**)&ql, g_q_lo);
    cudaGetSymbolAddress((void**)&kh, g_k_hi);  cudaGetSymbolAddress((void**)&kl, g_k_lo);
    cudaGetSymbolAddress((void**)&vh, g_v_hi);  cudaGetSymbolAddress((void**)&vl, g_v_lo);
    cudaGetSymbolAddress((void**)&ah, g_a_hi);  cudaGetSymbolAddress((void**)&al, g_a_lo);
    cudaGetSymbolAddress((void**)&wqh, g_wq_hi); cudaGetSymbolAddress((void**)&wql, g_wq_lo);
    cudaGetSymbolAddress((void**)&wkh, g_wk_hi); cudaGetSymbolAddress((void**)&wkl, g_wk_lo);
    cudaGetSymbolAddress((void**)&wvh, g_wv_hi); cudaGetSymbolAddress((void**)&wvl, g_wv_lo);
    cudaGetSymbolAddress((void**)&woh, g_wo_hi); cudaGetSymbolAddress((void**)&wol, g_wo_lo);
    cudaGetSymbolAddress((void**)&gatt, g_att);

    const int nAct4 = MTOK * D_ / 4;   // 1M vec4
    const int nW4   = D_ * D_ / 4;     // 256K vec4

    split_bf16_kernel<<<nAct4 / 256, 256>>>(q, qh, ql, nAct4);
    split_bf16_kernel<<<nAct4 / 256, 256>>>(k, kh, kl, nAct4);
    split_bf16_kernel<<<nAct4 / 256, 256>>>(v, vh, vl, nAct4);
    split_bf16_kernel<<<nW4 / 256, 256>>>(Wq, wqh, wql, nW4);
    split_bf16_kernel<<<nW4 / 256, 256>>>(Wk, wkh, wkl, nW4);
    split_bf16_kernel<<<nW4 / 256, 256>>>(Wv, wvh, wvl, nW4);
    split_bf16_kernel<<<nW4 / 256, 256>>>(Wo, woh, wol, nW4);

    dim3 gg(MTOK / GTM, D_ / GTN);     // 32 x 8 = 256 CTAs
    gemm_hmma_kernel<<<gg, 256, GEMM_SMEM>>>(qh, ql, wqh, wql, bq, nullptr, 0);
    gemm_hmma_kernel<<<gg, 256, GEMM_SMEM>>>(kh, kl, wkh, wkl, bk, nullptr, 1);
    gemm_hmma_kernel<<<gg, 256, GEMM_SMEM>>>(vh, vl, wvh, wvl, bv, nullptr, 2);

    dim3 gf(S_ / 64, H_, B_);          // 32 x 16 x 2
    flash_kernel<<<gf, 256, fl_smem>>>();

    split_bf16_kernel<<<nAct4 / 256, 256>>>(gatt, ah, al, nAct4);
    gemm_hmma_kernel<<<gg, 256, GEMM_SMEM>>>(ah, al, woh, wol, bo, out, 3);
}

// round 5
// speedup vs baseline: 2.3090x; 1.5872x over previous
#include <cuda_runtime.h>
#include <cuda_bf16.h>
#include <cstdint>

// Problem constants
#define B_   2
#define S_   2048
#define D_   1024
#define H_   16
#define HD_  64
#define MTOK (B_ * S_)      // 4096 tokens
#define SCALE_ 0.125f       // 64^-0.5

// ---------------------------------------------------------------------------
// Device-global scratch (no cudaMalloc allowed)
// ---------------------------------------------------------------------------
// bf16 splits of kernel inputs (GEMM A/W operands)
__device__ __nv_bfloat16 g_q_hi[(size_t)MTOK * D_],  g_q_lo[(size_t)MTOK * D_];
__device__ __nv_bfloat16 g_k_hi[(size_t)MTOK * D_],  g_k_lo[(size_t)MTOK * D_];
__device__ __nv_bfloat16 g_v_hi[(size_t)MTOK * D_],  g_v_lo[(size_t)MTOK * D_];
__device__ __nv_bfloat16 g_a_hi[(size_t)MTOK * D_],  g_a_lo[(size_t)MTOK * D_];
__device__ __nv_bfloat16 g_wq_hi[(size_t)D_ * D_],   g_wq_lo[(size_t)D_ * D_];
__device__ __nv_bfloat16 g_wk_hi[(size_t)D_ * D_],   g_wk_lo[(size_t)D_ * D_];
__device__ __nv_bfloat16 g_wv_hi[(size_t)D_ * D_],   g_wv_lo[(size_t)D_ * D_];
__device__ __nv_bfloat16 g_wo_hi[(size_t)D_ * D_],   g_wo_lo[(size_t)D_ * D_];
// bf16 hi/lo projected heads [B,H,S,HD] (written by GEMM epilogue, read by flash)
__device__ __nv_bfloat16 g_qhh[(size_t)MTOK * D_],   g_qhl[(size_t)MTOK * D_];
__device__ __nv_bfloat16 g_khh[(size_t)MTOK * D_],   g_khl[(size_t)MTOK * D_];
__device__ __nv_bfloat16 g_vhh[(size_t)MTOK * D_],   g_vhl[(size_t)MTOK * D_];

// ---------------------------------------------------------------------------
// Helpers
// ---------------------------------------------------------------------------
__device__ __forceinline__ uint32_t smem_u32(const void* p) {
    uint32_t a;
    asm("{ .reg .u64 t; cvta.to.shared.u64 t, %1; cvt.u32.u64 %0, t; }"
        : "=r"(a) : "l"(p));
    return a;
}

#define SWZ128(off) ((uint32_t)(off) ^ ((((uint32_t)(off)) >> 3) & 0x70u))

__device__ __forceinline__ void ldm_x4(uint32_t r[4], uint32_t addr) {
    asm volatile("ldmatrix.sync.aligned.m8n8.x4.shared.b16 {%0,%1,%2,%3}, [%4];"
        : "=r"(r[0]), "=r"(r[1]), "=r"(r[2]), "=r"(r[3]) : "r"(addr));
}
__device__ __forceinline__ void ldm_x4t(uint32_t r[4], uint32_t addr) {
    asm volatile("ldmatrix.sync.aligned.m8n8.x4.trans.shared.b16 {%0,%1,%2,%3}, [%4];"
        : "=r"(r[0]), "=r"(r[1]), "=r"(r[2]), "=r"(r[3]) : "r"(addr));
}

__device__ __forceinline__ void mma_bf16(float c[4], const uint32_t a[4],
                                         uint32_t b0, uint32_t b1) {
    asm volatile(
        "mma.sync.aligned.m16n8k16.row.col.f32.bf16.bf16.f32 "
        "{%0,%1,%2,%3}, {%4,%5,%6,%7}, {%8,%9}, {%0,%1,%2,%3};"
        : "+f"(c[0]), "+f"(c[1]), "+f"(c[2]), "+f"(c[3])
        : "r"(a[0]), "r"(a[1]), "r"(a[2]), "r"(a[3]), "r"(b0), "r"(b1));
}

__device__ __forceinline__ void cpa16(uint32_t s, const void* g) {
    asm volatile("cp.async.ca.shared.global [%0], [%1], 16;" :: "r"(s), "l"(g));
}
#define CPA_COMMIT() asm volatile("cp.async.commit_group;" ::: "memory")
#define CPA_WAIT0()  asm volatile("cp.async.wait_group 0;" ::: "memory")
#define CPA_WAIT1()  asm volatile("cp.async.wait_group 1;" ::: "memory")

// split float pair -> (hi bf16x2, lo bf16x2)
__device__ __forceinline__ uint32_t packsplit(float x, float y, uint32_t& lo) {
    __nv_bfloat16 hx = __float2bfloat16_rn(x), hy = __float2bfloat16_rn(y);
    __nv_bfloat16 lx = __float2bfloat16_rn(x - __bfloat162float(hx));
    __nv_bfloat16 ly = __float2bfloat16_rn(y - __bfloat162float(hy));
    lo = ((uint32_t)__bfloat16_as_ushort(ly) << 16) | __bfloat16_as_ushort(lx);
    return ((uint32_t)__bfloat16_as_ushort(hy) << 16) | __bfloat16_as_ushort(hx);
}

// ---------------------------------------------------------------------------
// fp32 -> (hi, lo) bf16 split, vectorized x4
// ---------------------------------------------------------------------------
__global__ __launch_bounds__(256) void split_bf16_kernel(
    const float* __restrict__ x,
    __nv_bfloat16* __restrict__ hi, __nv_bfloat16* __restrict__ lo, int n4)
{
    int i = blockIdx.x * blockDim.x + threadIdx.x;
    if (i >= n4) return;
    float4 v = ((const float4*)x)[i];
    float f[4] = {v.x, v.y, v.z, v.w};
    unsigned short hu[4], lu[4];
#pragma unroll
    for (int c = 0; c < 4; c++) {
        __nv_bfloat16 h = __float2bfloat16(f[c]);
        __nv_bfloat16 l = __float2bfloat16(f[c] - __bfloat162float(h));
        hu[c] = __bfloat16_as_ushort(h);
        lu[c] = __bfloat16_as_ushort(l);
    }
    ((ushort4*)hi)[i] = make_ushort4(hu[0], hu[1], hu[2], hu[3]);
    ((ushort4*)lo)[i] = make_ushort4(lu[0], lu[1], lu[2], lu[3]);
}

// ---------------------------------------------------------------------------
// HMMA bf16-split GEMM: C[M,N] = A[M,K] @ W[N,K]^T + bias
// out_mode 0/1/2: write bf16 hi/lo head layout [B,H,S,HD]; 3: fp32 Cext [M,N].
// ---------------------------------------------------------------------------
#define GTM 128
#define GTN 128
#define GK  1024
#define GEMM_SMEM 66560

__global__ __launch_bounds__(256) void gemm_hmma_kernel(
    const __nv_bfloat16* __restrict__ Ah, const __nv_bfloat16* __restrict__ Al,
    const __nv_bfloat16* __restrict__ Wh, const __nv_bfloat16* __restrict__ Wl,
    const float* __restrict__ bias, float* __restrict__ Cext, int out_mode)
{
    extern __shared__ char smem[];
    const uint32_t sb = smem_u32(smem);
    float* sbias = (float*)smem;

    const int tid  = threadIdx.x;
    const int lane = tid & 31;
    const int wid  = tid >> 5;
    const int warp_m = wid >> 2;
    const int warp_n = wid & 3;
    const int bm = blockIdx.x * GTM;
    const int bn = blockIdx.y * GTN;

    const uint32_t SA_HI = 1024;
    const uint32_t SA_LO = 17408;
    const uint32_t SW_HI = 33792;
    const uint32_t SW_LO = 50176;

    if (tid < GTN) sbias[tid] = bias[bn + tid];

    float acc[4][4][4];
#pragma unroll
    for (int a = 0; a < 4; a++)
#pragma unroll
        for (int b = 0; b < 4; b++)
#pragma unroll
            for (int c = 0; c < 4; c++) acc[a][b][c] = 0.f;

    for (int kc = 0; kc < GK / 64; kc++) {
        const int k0 = kc * 64;
#pragma unroll
        for (int v = tid; v < 1024; v += 256) {
            const int row = v >> 3, seg = v & 7;
            const uint32_t so = SWZ128(row * 128 + seg * 16);
            const size_t ga = (size_t)(bm + row) * GK + k0 + seg * 8;
            const size_t gw = (size_t)(bn + row) * GK + k0 + seg * 8;
            *(uint4*)(smem + SA_HI + so) = *(const uint4*)(Ah + ga);
            *(uint4*)(smem + SA_LO + so) = *(const uint4*)(Al + ga);
            *(uint4*)(smem + SW_HI + so) = *(const uint4*)(Wh + gw);
            *(uint4*)(smem + SW_LO + so) = *(const uint4*)(Wl + gw);
        }
        __syncthreads();

#pragma unroll
        for (int s = 0; s < 4; s++) {
            uint32_t ah[4][4], alr[4][4], bh[2][4], bl[2][4];
            const int arow = lane & 15;
            const int aseg = s * 2 + (lane >> 4);
#pragma unroll
            for (int t = 0; t < 4; t++) {
                const uint32_t off =
                    SWZ128((warp_m * 64 + t * 16 + arow) * 128 + aseg * 16);
                ldm_x4(ah[t],  sb + SA_HI + off);
                ldm_x4(alr[t], sb + SA_LO + off);
            }
            const int brow = (lane & 7) + ((lane & 16) >> 1);
            const int bseg = s * 2 + ((lane >> 3) & 1);
#pragma unroll
            for (int p = 0; p < 2; p++) {
                const uint32_t off =
                    SWZ128((warp_n * 32 + p * 16 + brow) * 128 + bseg * 16);
                ldm_x4(bh[p], sb + SW_HI + off);
                ldm_x4(bl[p], sb + SW_LO + off);
            }
#pragma unroll
            for (int mt = 0; mt < 4; mt++)
#pragma unroll
                for (int nt = 0; nt < 4; nt++) {
                    const int p = nt >> 1, q = (nt & 1) * 2;
                    mma_bf16(acc[mt][nt], ah[mt],  bh[p][q], bh[p][q + 1]);
                    mma_bf16(acc[mt][nt], ah[mt],  bl[p][q], bl[p][q + 1]);
                    mma_bf16(acc[mt][nt], alr[mt], bh[p][q], bh[p][q + 1]);
                }
        }
        __syncthreads();
    }

    const int group = lane >> 2, tg = lane & 3;
#pragma unroll
    for (int mt = 0; mt < 4; mt++) {
#pragma unroll
        for (int nt = 0; nt < 4; nt++) {
            const int m0 = bm + warp_m * 64 + mt * 16 + group;
            const int n0 = bn + warp_n * 32 + nt * 8 + tg * 2;
            const float bv0 = sbias[n0 - bn];
            const float bv1 = sbias[n0 - bn + 1];
            const float* cv = acc[mt][nt];
            if (out_mode < 3) {
                const int h = n0 >> 6, hd = n0 & 63;
                __nv_bfloat16* bhi = (out_mode == 0) ? g_qhh : (out_mode == 1) ? g_khh : g_vhh;
                __nv_bfloat16* blo = (out_mode == 0) ? g_qhl : (out_mode == 1) ? g_khl : g_vhl;
#pragma unroll
                for (int r = 0; r < 2; r++) {
                    const int m = m0 + r * 8;
                    const int b = m >> 11, sq = m & (S_ - 1);
                    uint32_t lo2;
                    uint32_t hi2 = packsplit(cv[r * 2 + 0] + bv0, cv[r * 2 + 1] + bv1, lo2);
                    const size_t off = ((size_t)(b * H_ + h) * S_ + sq) * HD_ + hd;
                    *(uint32_t*)(bhi + off) = hi2;
                    *(uint32_t*)(blo + off) = lo2;
                }
            } else {
#pragma unroll
                for (int r = 0; r < 2; r++) {
                    const int m = m0 + r * 8;
                    float2 w = make_float2(cv[r * 2 + 0] + bv0, cv[r * 2 + 1] + bv1);
                    *(float2*)(Cext + (size_t)m * D_ + n0) = w;
                }
            }
        }
    }
}

// ---------------------------------------------------------------------------
// HMMA flash attention, causal. Block = 128 queries x one (b,h), 256 threads.
// Warp w owns q rows [w*16, w*16+16). K-tile = 64 keys/iter, double-buffered
// via cp.async. 3-term bf16 split for both Q@K^T and P@V, fp32 softmax/accum.
// smem: stage s at s*32768: Khi(8K) Klo(8K) Vhi(8K) Vlo(8K). Q staged once.
// ---------------------------------------------------------------------------
#define FA_SMEM 65536

__global__ __launch_bounds__(256) void flash_hmma_kernel()
{
    extern __shared__ char fsm[];
    const uint32_t sb = smem_u32(fsm);
    const int tid = threadIdx.x, lane = tid & 31, w = tid >> 5;
    const int qt = (int)gridDim.x - 1 - (int)blockIdx.x;   // heavy tiles first
    const int h = blockIdx.y, b = blockIdx.z;
    const size_t hoff = (size_t)(b * H_ + h) * S_ * HD_;
    const __nv_bfloat16 *Qh = g_qhh + hoff, *Ql = g_qhl + hoff;
    const __nv_bfloat16 *Kh = g_khh + hoff, *Kl = g_khl + hoff;
    const __nv_bfloat16 *Vh = g_vhh + hoff, *Vl = g_vhl + hoff;
    const int q0 = qt * 128;

    // ---- stage Q (hi at sb, lo at sb+16K), build persistent Q fragments ----
    for (int u = tid; u < 1024; u += 256) {
        const int row = u >> 3, seg = u & 7;
        const uint32_t so = SWZ128(row * 128 + seg * 16);
        const size_t g = (size_t)(q0 + row) * HD_ + seg * 8;
        cpa16(sb + so,         Qh + g);
        cpa16(sb + 16384 + so, Ql + g);
    }
    CPA_COMMIT(); CPA_WAIT0(); __syncthreads();

    uint32_t qa[4][4], qlr[4][4];
    {
        const int arow = lane & 15, asel = lane >> 4;
#pragma unroll
        for (int s = 0; s < 4; s++) {
            const uint32_t off = SWZ128((w * 16 + arow) * 128 + (s * 2 + asel) * 16);
            ldm_x4(qa[s],  sb + off);
            ldm_x4(qlr[s], sb + 16384 + off);
        }
    }
    __syncthreads();

    const int n_iter = 2 * qt + 2;
    const int needed = ((q0 + w * 16 + 15) >> 6) + 1;   // per-warp live iters

    // fill(jt) -> stage st
    auto FILL = [&](int jt, int st) {
        const int k0 = jt * 64;
        const uint32_t base = sb + st * 32768;
        for (int u = tid; u < 512; u += 256) {
            const int row = u >> 3, seg = u & 7;
            const uint32_t so = SWZ128(row * 128 + seg * 16);
            const size_t g = (size_t)(k0 + row) * HD_ + seg * 8;
            cpa16(base + so,         Kh + g);
            cpa16(base + 8192 + so,  Kl + g);
            cpa16(base + 16384 + so, Vh + g);
            cpa16(base + 24576 + so, Vl + g);
        }
    };
    FILL(0, 0); CPA_COMMIT();
    if (n_iter > 1) FILL(1, 1);
    CPA_COMMIT();

    float m_s[2] = {-1e30f, -1e30f}, l_s[2] = {0.f, 0.f};
    float O[8][4];
#pragma unroll
    for (int nt = 0; nt < 8; nt++)
#pragma unroll
        for (int c = 0; c < 4; c++) O[nt][c] = 0.f;

    const int g_row = lane >> 2, tg = lane & 3;

    for (int jt = 0; jt < n_iter; jt++) {
        CPA_WAIT1();
        __syncthreads();
        const uint32_t kb = sb + (jt & 1) * 32768;

        if (jt < needed) {
            // ---- S = Q @ K^T (split 3-term) ----
            float sc[8][4];
#pragma unroll
            for (int nt = 0; nt < 8; nt++)
#pragma unroll
                for (int c = 0; c < 4; c++) sc[nt][c] = 0.f;

            const int brow = (lane & 7) + ((lane & 16) >> 1);
            const int bsel = (lane >> 3) & 1;
#pragma unroll
            for (int s = 0; s < 4; s++) {
#pragma unroll
                for (int p = 0; p < 4; p++) {
                    uint32_t kh4[4], kl4[4];
                    const uint32_t off =
                        SWZ128((p * 16 + brow) * 128 + (s * 2 + bsel) * 16);
                    ldm_x4(kh4, kb + off);
                    ldm_x4(kl4, kb + 8192 + off);
#pragma unroll
                    for (int t = 0; t < 2; t++) {
                        const int nt = p * 2 + t, q = t * 2;
                        mma_bf16(sc[nt], qa[s],  kh4[q], kh4[q + 1]);
                        mma_bf16(sc[nt], qa[s],  kl4[q], kl4[q + 1]);
                        mma_bf16(sc[nt], qlr[s], kh4[q], kh4[q + 1]);
                    }
                }
            }

            // ---- mask + online softmax (per-thread rows g, g+8) ----
            const bool maskit = (jt * 64 + 63) > (q0 + w * 16);
#pragma unroll
            for (int rr = 0; rr < 2; rr++) {
                const int qrow = q0 + w * 16 + g_row + rr * 8;
                float mx = -1e30f;
#pragma unroll
                for (int nt = 0; nt < 8; nt++) {
                    float v0 = sc[nt][rr * 2] * SCALE_;
                    float v1 = sc[nt][rr * 2 + 1] * SCALE_;
                    if (maskit) {
                        const int c0 = jt * 64 + nt * 8 + tg * 2;
                        if (c0 > qrow)     v0 = -1e30f;
                        if (c0 + 1 > qrow) v1 = -1e30f;
                    }
                    sc[nt][rr * 2] = v0; sc[nt][rr * 2 + 1] = v1;
                    mx = fmaxf(mx, fmaxf(v0, v1));
                }
                mx = fmaxf(mx, __shfl_xor_sync(0xffffffffu, mx, 1));
                mx = fmaxf(mx, __shfl_xor_sync(0xffffffffu, mx, 2));
                const float mn = fmaxf(m_s[rr], mx);
                const float f = __expf(m_s[rr] - mn);
                m_s[rr] = mn;
                float rs = 0.f;
#pragma unroll
                for (int nt = 0; nt < 8; nt++) {
                    float p0 = __expf(sc[nt][rr * 2] - mn);
                    float p1 = __expf(sc[nt][rr * 2 + 1] - mn);
                    sc[nt][rr * 2] = p0; sc[nt][rr * 2 + 1] = p1;
                    rs += p0 + p1;
                    O[nt][rr * 2] *= f; O[nt][rr * 2 + 1] *= f;
                }
                rs += __shfl_xor_sync(0xffffffffu, rs, 1);
                rs += __shfl_xor_sync(0xffffffffu, rs, 2);
                l_s[rr] = l_s[rr] * f + rs;
            }

            // ---- O += P @ V (split 3-term) ----
#pragma unroll
            for (int ks = 0; ks < 4; ks++) {
                uint32_t pah[4], pal[4];
                pah[0] = packsplit(sc[2 * ks][0],     sc[2 * ks][1],     pal[0]);
                pah[1] = packsplit(sc[2 * ks][2],     sc[2 * ks][3],     pal[1]);
                pah[2] = packsplit(sc[2 * ks + 1][0], sc[2 * ks + 1][1], pal[2]);
                pah[3] = packsplit(sc[2 * ks + 1][2], sc[2 * ks + 1][3], pal[3]);
#pragma unroll
                for (int np = 0; np < 4; np++) {
                    uint32_t vh4[4], vl4[4];
                    const uint32_t off = SWZ128((ks * 16 + (lane & 15)) * 128 +
                                                np * 32 + (lane >> 4) * 16);
                    ldm_x4t(vh4, kb + 16384 + off);
                    ldm_x4t(vl4, kb + 24576 + off);
#pragma unroll
                    for (int t = 0; t < 2; t++) {
                        const int nt = np * 2 + t, q = t * 2;
                        mma_bf16(O[nt], pah, vh4[q], vh4[q + 1]);
                        mma_bf16(O[nt], pah, vl4[q], vl4[q + 1]);
                        mma_bf16(O[nt], pal, vh4[q], vh4[q + 1]);
                    }
                }
            }
        }

        __syncthreads();
        const int nj = jt + 2;
        if (nj < n_iter) FILL(nj, jt & 1);
        CPA_COMMIT();
    }

    // ---- normalize + write split bf16 output [MTOK, D] ----
#pragma unroll
    for (int rr = 0; rr < 2; rr++) {
        const float inv = 1.f / l_s[rr];
        const int srow = q0 + w * 16 + g_row + rr * 8;
        const size_t rowbase = ((size_t)b * S_ + srow) * D_ + h * HD_;
#pragma unroll
        for (int nt = 0; nt < 8; nt++) {
            uint32_t lo2;
            uint32_t hi2 = packsplit(O[nt][rr * 2] * inv, O[nt][rr * 2 + 1] * inv, lo2);
            const size_t off = rowbase + nt * 8 + tg * 2;
            *(uint32_t*)(g_a_hi + off) = hi2;
            *(uint32_t*)(g_a_lo + off) = lo2;
        }
    }
}

// ---------------------------------------------------------------------------
// Launch.  Inputs: 0:q 1:k 2:v 3:attn_mask 4:Wq 5:bq 6:Wk 7:bk 8:Wv 9:bv 10:Wo 11:bo
// ---------------------------------------------------------------------------
extern "C" void kernel_launch(void* const* d_in, const int* in_sizes, int n_in,
                              void* d_out, int out_size)
{
    const float* q  = (const float*)d_in[0];
    const float* k  = (const float*)d_in[1];
    const float* v  = (const float*)d_in[2];
    const float* Wq = (const float*)d_in[4];
    const float* bq = (const float*)d_in[5];
    const float* Wk = (const float*)d_in[6];
    const float* bk = (const float*)d_in[7];
    const float* Wv = (const float*)d_in[8];
    const float* bv = (const float*)d_in[9];
    const float* Wo = (const float*)d_in[10];
    const float* bo = (const float*)d_in[11];
    float* out = (float*)d_out;

    static bool attr_done = false;
    if (!attr_done) {
        cudaFuncSetAttribute(gemm_hmma_kernel,
                             cudaFuncAttributeMaxDynamicSharedMemorySize, GEMM_SMEM);
        cudaFuncSetAttribute(flash_hmma_kernel,
                             cudaFuncAttributeMaxDynamicSharedMemorySize, FA_SMEM);
        attr_done = true;
    }

    __nv_bfloat16 *qh, *ql, *kh, *kl, *vh, *vl, *ah, *al;
    __nv_bfloat16 *wqh, *wql, *wkh, *wkl, *wvh, *wvl, *woh, *wol;
    cudaGetSymbolAddress((void**)&qh, g_q_hi);  cudaGetSymbolAddress((void**)&ql, g_q_lo);
    cudaGetSymbolAddress((void**)&kh, g_k_hi);  cudaGetSymbolAddress((void**)&kl, g_k_lo);
    cudaGetSymbolAddress((void**)&vh, g_v_hi);  cudaGetSymbolAddress((void**)&vl, g_v_lo);
    cudaGetSymbolAddress((void**)&ah, g_a_hi);  cudaGetSymbolAddress((void**)&al, g_a_lo);
    cudaGetSymbolAddress((void**)&wqh, g_wq_hi); cudaGetSymbolAddress((void**)&wql, g_wq_lo);
    cudaGetSymbolAddress((void**)&wkh, g_wk_hi); cudaGetSymbolAddress((void**)&wkl, g_wk_lo);
    cudaGetSymbolAddress((void**)&wvh, g_wv_hi); cudaGetSymbolAddress((void**)&wvl, g_wv_lo);
    cudaGetSymbolAddress((void**)&woh, g_wo_hi); cudaGetSymbolAddress((void**)&wol, g_wo_lo);

    const int nAct4 = MTOK * D_ / 4;
    const int nW4   = D_ * D_ / 4;

    split_bf16_kernel<<<nAct4 / 256, 256>>>(q, qh, ql, nAct4);
    split_bf16_kernel<<<nAct4 / 256, 256>>>(k, kh, kl, nAct4);
    split_bf16_kernel<<<nAct4 / 256, 256>>>(v, vh, vl, nAct4);
    split_bf16_kernel<<<nW4 / 256, 256>>>(Wq, wqh, wql, nW4);
    split_bf16_kernel<<<nW4 / 256, 256>>>(Wk, wkh, wkl, nW4);
    split_bf16_kernel<<<nW4 / 256, 256>>>(Wv, wvh, wvl, nW4);
    split_bf16_kernel<<<nW4 / 256, 256>>>(Wo, woh, wol, nW4);

    dim3 gg(MTOK / GTM, D_ / GTN);     // 32 x 8 = 256 CTAs
    gemm_hmma_kernel<<<gg, 256, GEMM_SMEM>>>(qh, ql, wqh, wql, bq, nullptr, 0);
    gemm_hmma_kernel<<<gg, 256, GEMM_SMEM>>>(kh, kl, wkh, wkl, bk, nullptr, 1);
    gemm_hmma_kernel<<<gg, 256, GEMM_SMEM>>>(vh, vl, wvh, wvl, bv, nullptr, 2);

    flash_hmma_kernel<<<dim3(S_ / 128, H_, B_), 256, FA_SMEM>>>();

    gemm_hmma_kernel<<<gg, 256, GEMM_SMEM>>>(ah, al, woh, wol, bo, out, 3);
}

// round 7
// speedup vs baseline: 3.1363x; 1.3583x over previous
#include <cuda_runtime.h>
#include <cuda_bf16.h>
#include <cstdint>

// Problem constants
#define B_   2
#define S_   2048
#define D_   1024
#define H_   16
#define HD_  64
#define MTOK (B_ * S_)      // 4096 tokens
#define SCALE_ 0.125f       // 64^-0.5

// ---------------------------------------------------------------------------
// Device-global scratch (no cudaMalloc allowed)
// ---------------------------------------------------------------------------
__device__ __nv_bfloat16 g_q_hi[(size_t)MTOK * D_],  g_q_lo[(size_t)MTOK * D_];
__device__ __nv_bfloat16 g_k_hi[(size_t)MTOK * D_],  g_k_lo[(size_t)MTOK * D_];
__device__ __nv_bfloat16 g_v_hi[(size_t)MTOK * D_],  g_v_lo[(size_t)MTOK * D_];
__device__ __nv_bfloat16 g_a_hi[(size_t)MTOK * D_],  g_a_lo[(size_t)MTOK * D_];
__device__ __nv_bfloat16 g_wq_hi[(size_t)D_ * D_],   g_wq_lo[(size_t)D_ * D_];
__device__ __nv_bfloat16 g_wk_hi[(size_t)D_ * D_],   g_wk_lo[(size_t)D_ * D_];
__device__ __nv_bfloat16 g_wv_hi[(size_t)D_ * D_],   g_wv_lo[(size_t)D_ * D_];
__device__ __nv_bfloat16 g_wo_hi[(size_t)D_ * D_],   g_wo_lo[(size_t)D_ * D_];
// bf16 hi/lo projected heads [B,H,S,HD]
__device__ __nv_bfloat16 g_qhh[(size_t)MTOK * D_],   g_qhl[(size_t)MTOK * D_];
__device__ __nv_bfloat16 g_khh[(size_t)MTOK * D_],   g_khl[(size_t)MTOK * D_];
__device__ __nv_bfloat16 g_vhh[(size_t)MTOK * D_],   g_vhl[(size_t)MTOK * D_];

// ---------------------------------------------------------------------------
// Helpers
// ---------------------------------------------------------------------------
__device__ __forceinline__ uint32_t smem_u32(const void* p) {
    uint32_t a;
    asm("{ .reg .u64 t; cvta.to.shared.u64 t, %1; cvt.u32.u64 %0, t; }"
        : "=r"(a) : "l"(p));
    return a;
}

#define SWZ128(off) ((uint32_t)(off) ^ ((((uint32_t)(off)) >> 3) & 0x70u))

__device__ __forceinline__ void ldm_x4(uint32_t r[4], uint32_t addr) {
    asm volatile("ldmatrix.sync.aligned.m8n8.x4.shared.b16 {%0,%1,%2,%3}, [%4];"
        : "=r"(r[0]), "=r"(r[1]), "=r"(r[2]), "=r"(r[3]) : "r"(addr));
}
__device__ __forceinline__ void ldm_x4t(uint32_t r[4], uint32_t addr) {
    asm volatile("ldmatrix.sync.aligned.m8n8.x4.trans.shared.b16 {%0,%1,%2,%3}, [%4];"
        : "=r"(r[0]), "=r"(r[1]), "=r"(r[2]), "=r"(r[3]) : "r"(addr));
}

__device__ __forceinline__ void mma_bf16(float c[4], const uint32_t a[4],
                                         uint32_t b0, uint32_t b1) {
    asm volatile(
        "mma.sync.aligned.m16n8k16.row.col.f32.bf16.bf16.f32 "
        "{%0,%1,%2,%3}, {%4,%5,%6,%7}, {%8,%9}, {%0,%1,%2,%3};"
        : "+f"(c[0]), "+f"(c[1]), "+f"(c[2]), "+f"(c[3])
        : "r"(a[0]), "r"(a[1]), "r"(a[2]), "r"(a[3]), "r"(b0), "r"(b1));
}

__device__ __forceinline__ void cpa16(uint32_t s, const void* g) {
    asm volatile("cp.async.ca.shared.global [%0], [%1], 16;" :: "r"(s), "l"(g));
}
#define CPA_COMMIT() asm volatile("cp.async.commit_group;" ::: "memory")
#define CPA_WAIT0()  asm volatile("cp.async.wait_group 0;" ::: "memory")
#define CPA_WAIT1()  asm volatile("cp.async.wait_group 1;" ::: "memory")

// split float pair -> (hi bf16x2, lo bf16x2)
__device__ __forceinline__ uint32_t packsplit(float x, float y, uint32_t& lo) {
    __nv_bfloat16 hx = __float2bfloat16_rn(x), hy = __float2bfloat16_rn(y);
    __nv_bfloat16 lx = __float2bfloat16_rn(x - __bfloat162float(hx));
    __nv_bfloat16 ly = __float2bfloat16_rn(y - __bfloat162float(hy));
    lo = ((uint32_t)__bfloat16_as_ushort(ly) << 16) | __bfloat16_as_ushort(lx);
    return ((uint32_t)__bfloat16_as_ushort(hy) << 16) | __bfloat16_as_ushort(hx);
}

// ---------------------------------------------------------------------------
// fp32 -> (hi, lo) bf16 split, vectorized x4
// ---------------------------------------------------------------------------
__global__ __launch_bounds__(256) void split_bf16_kernel(
    const float* __restrict__ x,
    __nv_bfloat16* __restrict__ hi, __nv_bfloat16* __restrict__ lo, int n4)
{
    int i = blockIdx.x * blockDim.x + threadIdx.x;
    if (i >= n4) return;
    float4 v = ((const float4*)x)[i];
    float f[4] = {v.x, v.y, v.z, v.w};
    unsigned short hu[4], lu[4];
#pragma unroll
    for (int c = 0; c < 4; c++) {
        __nv_bfloat16 h = __float2bfloat16(f[c]);
        __nv_bfloat16 l = __float2bfloat16(f[c] - __bfloat162float(h));
        hu[c] = __bfloat16_as_ushort(h);
        lu[c] = __bfloat16_as_ushort(l);
    }
    ((ushort4*)hi)[i] = make_ushort4(hu[0], hu[1], hu[2], hu[3]);
    ((ushort4*)lo)[i] = make_ushort4(lu[0], lu[1], lu[2], lu[3]);
}

// ---------------------------------------------------------------------------
// HMMA bf16-split GEMM, cp.async 2-stage pipelined mainloop.
// C[M,N] = A[M,K] @ W[N,K]^T + bias; CTA tile 128x128, k-chunk 64.
// out_mode 0/1/2: bf16 hi/lo head layout [B,H,S,HD]; 3: fp32 Cext [M,N].
// smem: 1KB bias | stage0 (4 x 16KB) | stage1 (4 x 16KB) = 132096 B
// ---------------------------------------------------------------------------
#define GTM 128
#define GTN 128
#define GK  1024
#define STG_BYTES 65536
#define GEMM_SMEM (1024 + 2 * STG_BYTES)

__global__ __launch_bounds__(256) void gemm_hmma_kernel(
    const __nv_bfloat16* __restrict__ Ah, const __nv_bfloat16* __restrict__ Al,
    const __nv_bfloat16* __restrict__ Wh, const __nv_bfloat16* __restrict__ Wl,
    const float* __restrict__ bias, float* __restrict__ Cext, int out_mode)
{
    extern __shared__ char smem[];
    const uint32_t sb = smem_u32(smem);
    float* sbias = (float*)smem;

    const int tid  = threadIdx.x;
    const int lane = tid & 31;
    const int wid  = tid >> 5;
    const int warp_m = wid >> 2;
    const int warp_n = wid & 3;
    const int bm = blockIdx.x * GTM;
    const int bn = blockIdx.y * GTN;

    if (tid < GTN) sbias[tid] = bias[bn + tid];

    // per-thread fixed load slots: 4 vec16 per tile (1024 vec16 / 256 thr)
    const int lrow0 = tid >> 3, lseg = tid & 7;      // rows lrow0, +32, +64, +96

    auto FILL = [&](int kc, int st) {
        const int k0 = kc * 64;
        const uint32_t base = sb + 1024 + st * STG_BYTES;
#pragma unroll
        for (int r = 0; r < 4; r++) {
            const int row = lrow0 + r * 32;
            const uint32_t so = SWZ128(row * 128 + lseg * 16);
            const size_t ga = (size_t)(bm + row) * GK + k0 + lseg * 8;
            const size_t gw = (size_t)(bn + row) * GK + k0 + lseg * 8;
            cpa16(base + so,         Ah + ga);
            cpa16(base + 16384 + so, Al + ga);
            cpa16(base + 32768 + so, Wh + gw);
            cpa16(base + 49152 + so, Wl + gw);
        }
    };

    float acc[4][4][4];
#pragma unroll
    for (int a = 0; a < 4; a++)
#pragma unroll
        for (int b = 0; b < 4; b++)
#pragma unroll
            for (int c = 0; c < 4; c++) acc[a][b][c] = 0.f;

    FILL(0, 0); CPA_COMMIT();
    FILL(1, 1); CPA_COMMIT();

    for (int kc = 0; kc < GK / 64; kc++) {
        CPA_WAIT1();
        __syncthreads();
        const uint32_t SA_HI = sb + 1024 + (kc & 1) * STG_BYTES;
        const uint32_t SA_LO = SA_HI + 16384;
        const uint32_t SW_HI = SA_HI + 32768;
        const uint32_t SW_LO = SA_HI + 49152;

#pragma unroll
        for (int s = 0; s < 4; s++) {
            uint32_t ah[4][4], alr[4][4], bh[2][4], bl[2][4];
            const int arow = lane & 15;
            const int aseg = s * 2 + (lane >> 4);
#pragma unroll
            for (int t = 0; t < 4; t++) {
                const uint32_t off =
                    SWZ128((warp_m * 64 + t * 16 + arow) * 128 + aseg * 16);
                ldm_x4(ah[t],  SA_HI + off);
                ldm_x4(alr[t], SA_LO + off);
            }
            const int brow = (lane & 7) + ((lane & 16) >> 1);
            const int bseg = s * 2 + ((lane >> 3) & 1);
#pragma unroll
            for (int p = 0; p < 2; p++) {
                const uint32_t off =
                    SWZ128((warp_n * 32 + p * 16 + brow) * 128 + bseg * 16);
                ldm_x4(bh[p], SW_HI + off);
                ldm_x4(bl[p], SW_LO + off);
            }
#pragma unroll
            for (int mt = 0; mt < 4; mt++)
#pragma unroll
                for (int nt = 0; nt < 4; nt++) {
                    const int p = nt >> 1, q = (nt & 1) * 2;
                    mma_bf16(acc[mt][nt], ah[mt],  bh[p][q], bh[p][q + 1]);
                    mma_bf16(acc[mt][nt], ah[mt],  bl[p][q], bl[p][q + 1]);
                    mma_bf16(acc[mt][nt], alr[mt], bh[p][q], bh[p][q + 1]);
                }
        }

        __syncthreads();
        if (kc + 2 < GK / 64) { FILL(kc + 2, kc & 1); CPA_COMMIT(); }
    }

    const int group = lane >> 2, tg = lane & 3;
#pragma unroll
    for (int mt = 0; mt < 4; mt++) {
#pragma unroll
        for (int nt = 0; nt < 4; nt++) {
            const int m0 = bm + warp_m * 64 + mt * 16 + group;
            const int n0 = bn + warp_n * 32 + nt * 8 + tg * 2;
            const float bv0 = sbias[n0 - bn];
            const float bv1 = sbias[n0 - bn + 1];
            const float* cv = acc[mt][nt];
            if (out_mode < 3) {
                const int h = n0 >> 6, hd = n0 & 63;
                __nv_bfloat16* bhi = (out_mode == 0) ? g_qhh : (out_mode == 1) ? g_khh : g_vhh;
                __nv_bfloat16* blo = (out_mode == 0) ? g_qhl : (out_mode == 1) ? g_khl : g_vhl;
#pragma unroll
                for (int r = 0; r < 2; r++) {
                    const int m = m0 + r * 8;
                    const int b = m >> 11, sq = m & (S_ - 1);
                    uint32_t lo2;
                    uint32_t hi2 = packsplit(cv[r * 2 + 0] + bv0, cv[r * 2 + 1] + bv1, lo2);
                    const size_t off = ((size_t)(b * H_ + h) * S_ + sq) * HD_ + hd;
                    *(uint32_t*)(bhi + off) = hi2;
                    *(uint32_t*)(blo + off) = lo2;
                }
            } else {
#pragma unroll
                for (int r = 0; r < 2; r++) {
                    const int m = m0 + r * 8;
                    float2 w = make_float2(cv[r * 2 + 0] + bv0, cv[r * 2 + 1] + bv1);
                    *(float2*)(Cext + (size_t)m * D_ + n0) = w;
                }
            }
        }
    }
}

// ---------------------------------------------------------------------------
// HMMA flash attention, causal (unchanged from R5 — verified).
// ---------------------------------------------------------------------------
#define FA_SMEM 65536

__global__ __launch_bounds__(256) void flash_hmma_kernel()
{
    extern __shared__ char fsm[];
    const uint32_t sb = smem_u32(fsm);
    const int tid = threadIdx.x, lane = tid & 31, w = tid >> 5;
    const int qt = (int)gridDim.x - 1 - (int)blockIdx.x;
    const int h = blockIdx.y, b = blockIdx.z;
    const size_t hoff = (size_t)(b * H_ + h) * S_ * HD_;
    const __nv_bfloat16 *Qh = g_qhh + hoff, *Ql = g_qhl + hoff;
    const __nv_bfloat16 *Kh = g_khh + hoff, *Kl = g_khl + hoff;
    const __nv_bfloat16 *Vh = g_vhh + hoff, *Vl = g_vhl + hoff;
    const int q0 = qt * 128;

    for (int u = tid; u < 1024; u += 256) {
        const int row = u >> 3, seg = u & 7;
        const uint32_t so = SWZ128(row * 128 + seg * 16);
        const size_t g = (size_t)(q0 + row) * HD_ + seg * 8;
        cpa16(sb + so,         Qh + g);
        cpa16(sb + 16384 + so, Ql + g);
    }
    CPA_COMMIT(); CPA_WAIT0(); __syncthreads();

    uint32_t qa[4][4], qlr[4][4];
    {
        const int arow = lane & 15, asel = lane >> 4;
#pragma unroll
        for (int s = 0; s < 4; s++) {
            const uint32_t off = SWZ128((w * 16 + arow) * 128 + (s * 2 + asel) * 16);
            ldm_x4(qa[s],  sb + off);
            ldm_x4(qlr[s], sb + 16384 + off);
        }
    }
    __syncthreads();

    const int n_iter = 2 * qt + 2;
    const int needed = ((q0 + w * 16 + 15) >> 6) + 1;

    auto FILL = [&](int jt, int st) {
        const int k0 = jt * 64;
        const uint32_t base = sb + st * 32768;
        for (int u = tid; u < 512; u += 256) {
            const int row = u >> 3, seg = u & 7;
            const uint32_t so = SWZ128(row * 128 + seg * 16);
            const size_t g = (size_t)(k0 + row) * HD_ + seg * 8;
            cpa16(base + so,         Kh + g);
            cpa16(base + 8192 + so,  Kl + g);
            cpa16(base + 16384 + so, Vh + g);
            cpa16(base + 24576 + so, Vl + g);
        }
    };
    FILL(0, 0); CPA_COMMIT();
    if (n_iter > 1) FILL(1, 1);
    CPA_COMMIT();

    float m_s[2] = {-1e30f, -1e30f}, l_s[2] = {0.f, 0.f};
    float O[8][4];
#pragma unroll
    for (int nt = 0; nt < 8; nt++)
#pragma unroll
        for (int c = 0; c < 4; c++) O[nt][c] = 0.f;

    const int g_row = lane >> 2, tg = lane & 3;

    for (int jt = 0; jt < n_iter; jt++) {
        CPA_WAIT1();
        __syncthreads();
        const uint32_t kb = sb + (jt & 1) * 32768;

        if (jt < needed) {
            float sc[8][4];
#pragma unroll
            for (int nt = 0; nt < 8; nt++)
#pragma unroll
                for (int c = 0; c < 4; c++) sc[nt][c] = 0.f;

            const int brow = (lane & 7) + ((lane & 16) >> 1);
            const int bsel = (lane >> 3) & 1;
#pragma unroll
            for (int s = 0; s < 4; s++) {
#pragma unroll
                for (int p = 0; p < 4; p++) {
                    uint32_t kh4[4], kl4[4];
                    const uint32_t off =
                        SWZ128((p * 16 + brow) * 128 + (s * 2 + bsel) * 16);
                    ldm_x4(kh4, kb + off);
                    ldm_x4(kl4, kb + 8192 + off);
#pragma unroll
                    for (int t = 0; t < 2; t++) {
                        const int nt = p * 2 + t, q = t * 2;
                        mma_bf16(sc[nt], qa[s],  kh4[q], kh4[q + 1]);
                        mma_bf16(sc[nt], qa[s],  kl4[q], kl4[q + 1]);
                        mma_bf16(sc[nt], qlr[s], kh4[q], kh4[q + 1]);
                    }
                }
            }

            const bool maskit = (jt * 64 + 63) > (q0 + w * 16);
#pragma unroll
            for (int rr = 0; rr < 2; rr++) {
                const int qrow = q0 + w * 16 + g_row + rr * 8;
                float mx = -1e30f;
#pragma unroll
                for (int nt = 0; nt < 8; nt++) {
                    float v0 = sc[nt][rr * 2] * SCALE_;
                    float v1 = sc[nt][rr * 2 + 1] * SCALE_;
                    if (maskit) {
                        const int c0 = jt * 64 + nt * 8 + tg * 2;
                        if (c0 > qrow)     v0 = -1e30f;
                        if (c0 + 1 > qrow) v1 = -1e30f;
                    }
                    sc[nt][rr * 2] = v0; sc[nt][rr * 2 + 1] = v1;
                    mx = fmaxf(mx, fmaxf(v0, v1));
                }
                mx = fmaxf(mx, __shfl_xor_sync(0xffffffffu, mx, 1));
                mx = fmaxf(mx, __shfl_xor_sync(0xffffffffu, mx, 2));
                const float mn = fmaxf(m_s[rr], mx);
                const float f = __expf(m_s[rr] - mn);
                m_s[rr] = mn;
                float rs = 0.f;
#pragma unroll
                for (int nt = 0; nt < 8; nt++) {
                    float p0 = __expf(sc[nt][rr * 2] - mn);
                    float p1 = __expf(sc[nt][rr * 2 + 1] - mn);
                    sc[nt][rr * 2] = p0; sc[nt][rr * 2 + 1] = p1;
                    rs += p0 + p1;
                    O[nt][rr * 2] *= f; O[nt][rr * 2 + 1] *= f;
                }
                rs += __shfl_xor_sync(0xffffffffu, rs, 1);
                rs += __shfl_xor_sync(0xffffffffu, rs, 2);
                l_s[rr] = l_s[rr] * f + rs;
            }

#pragma unroll
            for (int ks = 0; ks < 4; ks++) {
                uint32_t pah[4], pal[4];
                pah[0] = packsplit(sc[2 * ks][0],     sc[2 * ks][1],     pal[0]);
                pah[1] = packsplit(sc[2 * ks][2],     sc[2 * ks][3],     pal[1]);
                pah[2] = packsplit(sc[2 * ks + 1][0], sc[2 * ks + 1][1], pal[2]);
                pah[3] = packsplit(sc[2 * ks + 1][2], sc[2 * ks + 1][3], pal[3]);
#pragma unroll
                for (int np = 0; np < 4; np++) {
                    uint32_t vh4[4], vl4[4];
                    const uint32_t off = SWZ128((ks * 16 + (lane & 15)) * 128 +
                                                np * 32 + (lane >> 4) * 16);
                    ldm_x4t(vh4, kb + 16384 + off);
                    ldm_x4t(vl4, kb + 24576 + off);
#pragma unroll
                    for (int t = 0; t < 2; t++) {
                        const int nt = np * 2 + t, q = t * 2;
                        mma_bf16(O[nt], pah, vh4[q], vh4[q + 1]);
                        mma_bf16(O[nt], pah, vl4[q], vl4[q + 1]);
                        mma_bf16(O[nt], pal, vh4[q], vh4[q + 1]);
                    }
                }
            }
        }

        __syncthreads();
        const int nj = jt + 2;
        if (nj < n_iter) FILL(nj, jt & 1);
        CPA_COMMIT();
    }

#pragma unroll
    for (int rr = 0; rr < 2; rr++) {
        const float inv = 1.f / l_s[rr];
        const int srow = q0 + w * 16 + g_row + rr * 8;
        const size_t rowbase = ((size_t)b * S_ + srow) * D_ + h * HD_;
#pragma unroll
        for (int nt = 0; nt < 8; nt++) {
            uint32_t lo2;
            uint32_t hi2 = packsplit(O[nt][rr * 2] * inv, O[nt][rr * 2 + 1] * inv, lo2);
            const size_t off = rowbase + nt * 8 + tg * 2;
            *(uint32_t*)(g_a_hi + off) = hi2;
            *(uint32_t*)(g_a_lo + off) = lo2;
        }
    }
}

// ---------------------------------------------------------------------------
// Launch.  Inputs: 0:q 1:k 2:v 3:attn_mask 4:Wq 5:bq 6:Wk 7:bk 8:Wv 9:bv 10:Wo 11:bo
// ---------------------------------------------------------------------------
extern "C" void kernel_launch(void* const* d_in, const int* in_sizes, int n_in,
                              void* d_out, int out_size)
{
    const float* q  = (const float*)d_in[0];
    const float* k  = (const float*)d_in[1];
    const float* v  = (const float*)d_in[2];
    const float* Wq = (const float*)d_in[4];
    const float* bq = (const float*)d_in[5];
    const float* Wk = (const float*)d_in[6];
    const float* bk = (const float*)d_in[7];
    const float* Wv = (const float*)d_in[8];
    const float* bv = (const float*)d_in[9];
    const float* Wo = (const float*)d_in[10];
    const float* bo = (const float*)d_in[11];
    float* out = (float*)d_out;

    static bool attr_done = false;
    if (!attr_done) {
        cudaFuncSetAttribute(gemm_hmma_kernel,
                             cudaFuncAttributeMaxDynamicSharedMemorySize, GEMM_SMEM);
        cudaFuncSetAttribute(flash_hmma_kernel,
                             cudaFuncAttributeMaxDynamicSharedMemorySize, FA_SMEM);
        attr_done = true;
    }

    __nv_bfloat16 *qh, *ql, *kh, *kl, *vh, *vl, *ah, *al;
    __nv_bfloat16 *wqh, *wql, *wkh, *wkl, *wvh, *wvl, *woh, *wol;
    cudaGetSymbolAddress((void**)&qh, g_q_hi);  cudaGetSymbolAddress((void**)&ql, g_q_lo);
    cudaGetSymbolAddress((void**)&kh, g_k_hi);  cudaGetSymbolAddress((void**)&kl, g_k_lo);
    cudaGetSymbolAddress((void**)&vh, g_v_hi);  cudaGetSymbolAddress((void**)&vl, g_v_lo);
    cudaGetSymbolAddress((void**)&ah, g_a_hi);  cudaGetSymbolAddress((void**)&al, g_a_lo);
    cudaGetSymbolAddress((void**)&wqh, g_wq_hi); cudaGetSymbolAddress((void**)&wql, g_wq_lo);
    cudaGetSymbolAddress((void**)&wkh, g_wk_hi); cudaGetSymbolAddress((void**)&wkl, g_wk_lo);
    cudaGetSymbolAddress((void**)&wvh, g_wv_hi); cudaGetSymbolAddress((void**)&wvl, g_wv_lo);
    cudaGetSymbolAddress((void**)&woh, g_wo_hi); cudaGetSymbolAddress((void**)&wol, g_wo_lo);

    const int nAct4 = MTOK * D_ / 4;
    const int nW4   = D_ * D_ / 4;

    split_bf16_kernel<<<nAct4 / 256, 256>>>(q, qh, ql, nAct4);
    split_bf16_kernel<<<nAct4 / 256, 256>>>(k, kh, kl, nAct4);
    split_bf16_kernel<<<nAct4 / 256, 256>>>(v, vh, vl, nAct4);
    split_bf16_kernel<<<nW4 / 256, 256>>>(Wq, wqh, wql, nW4);
    split_bf16_kernel<<<nW4 / 256, 256>>>(Wk, wkh, wkl, nW4);
    split_bf16_kernel<<<nW4 / 256, 256>>>(Wv, wvh, wvl, nW4);
    split_bf16_kernel<<<nW4 / 256, 256>>>(Wo, woh, wol, nW4);

    dim3 gg(MTOK / GTM, D_ / GTN);     // 32 x 8 = 256 CTAs
    gemm_hmma_kernel<<<gg, 256, GEMM_SMEM>>>(qh, ql, wqh, wql, bq, nullptr, 0);
    gemm_hmma_kernel<<<gg, 256, GEMM_SMEM>>>(kh, kl, wkh, wkl, bk, nullptr, 1);
    gemm_hmma_kernel<<<gg, 256, GEMM_SMEM>>>(vh, vl, wvh, wvl, bv, nullptr, 2);

    flash_hmma_kernel<<<dim3(S_ / 128, H_, B_), 256, FA_SMEM>>>();

    gemm_hmma_kernel<<<gg, 256, GEMM_SMEM>>>(ah, al, woh, wol, bo, out, 3);
}